// round 16
// baseline (speedup 1.0000x reference)
#include <cuda_runtime.h>
#include <cuda_fp16.h>
#include <cstdint>

// ---------------------------------------------------------------------------
// AUGRU cell, sm_103 base-PTX path (no tcgen05 via compute_103).
// mma.sync.m16n8k16 fp16->fp32, persistent CTAs, fp16 weights resident in
// SMEM (paired granule-XOR layout), activations staged per 64-row tile.
//
// R16 vs R14 (best: 57.86us): ONE change -- the first per-half barrier moves
// from after-the-epilogue to immediately after the MMA loop. Act SMEM is
// dead once the MMA loop ends (h fragment captured in-loop at i==0), so the
// WAR barrier can fire there, removing the epilogue (~1.5K cyc MUFU/STG +
// warp skew) from the staging critical path. Everything else R14-verbatim:
// ldmatrix A path + double-XOR act layout, paired B LDS.64 granule-XOR,
// kt rotation, staggered x/h prefetch around the epilogue, register-local
// epilogue, 2 half-barriers/tile.
//
// Warp map: w = mh*8+ws; mh = 32-row half, ws = 16-col strip.
// acc[gate 0..3][mt 0..1][j 0..1][4]; gates: 0=u, 1=r, 2=x_h, 3=h_h.
// ---------------------------------------------------------------------------

#define HID 128

// SMEM layout (bytes)
#define OFF_WX   0                    // 48 nt * 8 kt * 256 = 98304 (paired)
#define OFF_WH   98304
#define OFF_BIAS 196608               // 512 floats = 2048
#define OFF_X    198656               // act blocks: (mt*8+kt)*512, 16384 B
#define OFF_H    215040
#define SMEM_TOTAL 231424

static __device__ __forceinline__ uint32_t h2u(__half2 h) {
    return *reinterpret_cast<uint32_t*>(&h);
}
static __device__ __forceinline__ __half2 u2h(uint32_t u) {
    return *reinterpret_cast<__half2*>(&u);
}

static __device__ __forceinline__ uint32_t smem_u32(const void* p) {
    uint32_t a;
    asm("{ .reg .u64 t; cvta.to.shared.u64 t, %1; cvt.u32.u64 %0, t; }"
        : "=r"(a) : "l"(p));
    return a;
}

static __device__ __forceinline__ float tanh_fast(float z) {
    float y;
    asm("tanh.approx.f32 %0, %1;" : "=f"(y) : "f"(z));
    return y;
}
static __device__ __forceinline__ float sigmoid_fast(float z) {
    return fmaf(tanh_fast(0.5f * z), 0.5f, 0.5f);
}

static __device__ __forceinline__ void mma16816(float* c, const uint32_t* a,
                                                uint32_t b0, uint32_t b1) {
    asm volatile(
        "mma.sync.aligned.m16n8k16.row.col.f32.f16.f16.f32 "
        "{%0,%1,%2,%3}, {%4,%5,%6,%7}, {%8,%9}, {%0,%1,%2,%3};"
        : "+f"(c[0]), "+f"(c[1]), "+f"(c[2]), "+f"(c[3])
        : "r"(a[0]), "r"(a[1]), "r"(a[2]), "r"(a[3]), "r"(b0), "r"(b1));
}

static __device__ __forceinline__ void ldmx4(uint32_t* f, uint32_t addr) {
    asm volatile(
        "ldmatrix.sync.aligned.m8n8.x4.shared.b16 {%0,%1,%2,%3}, [%4];"
        : "=r"(f[0]), "=r"(f[1]), "=r"(f[2]), "=r"(f[3]) : "r"(addr));
}

static __device__ __forceinline__ void bar_half(int mh) {
    asm volatile("bar.sync %0, %1;" :: "r"(1 + mh), "r"(256) : "memory");
}

// act fragment block base (512B blocks, disjoint)
static __device__ __forceinline__ uint32_t ablk(int mt, int kt) {
    return (uint32_t)((mt * 8 + kt) * 512);
}

// W fp32 [384,128] row-major -> fp16 B-fragment PAIRED block layout (R11).
// Block (kt, nt) = 256 B at (nt*8 + kt)*256. Lane slot (col g, pair t):
//   offset ((g^kt)&7)*32 + t*8 ; [0:4)=b0 pair (k=2t,2t+1), [4:8)=b1 pair.
static __device__ __forceinline__ void conv_weight(char* smem, uint32_t off,
                                                   const float* __restrict__ W) {
    for (int it = threadIdx.x; it < 384 * 32; it += 512) {
        int n = it >> 5;
        int k4 = (it & 31) << 2;
        int kt = k4 >> 4;
        float4 v = *reinterpret_cast<const float4*>(W + (size_t)n * 128 + k4);
        uint32_t p0 = h2u(__floats2half2_rn(v.x, v.y));
        uint32_t p1 = h2u(__floats2half2_rn(v.z, v.w));
        int t0 = (k4 & 7) >> 1;                           // 0 or 2
        uint32_t hi = (k4 & 8) ? 4u : 0u;                 // b0 vs b1
        uint32_t base = off + (uint32_t)(((n >> 3) * 8 + kt) * 256)
                      + ((uint32_t)((n ^ kt) & 7) << 5) + hi;
        *reinterpret_cast<uint32_t*>(smem + base + (uint32_t)t0 * 8)       = p0;
        *reinterpret_cast<uint32_t*>(smem + base + (uint32_t)(t0 + 1) * 8) = p1;
    }
}

__global__ void __launch_bounds__(512, 1) augru_kernel(
    const float* __restrict__ x, const float* __restrict__ h_prev,
    const float* __restrict__ att, const float* __restrict__ Wx,
    const float* __restrict__ bx, const float* __restrict__ Wh,
    const float* __restrict__ bh, float* __restrict__ out, int ntiles)
{
    extern __shared__ char smem[];
    const uint32_t sb32 = smem_u32(smem);
    const int tid = threadIdx.x;
    const int w = tid >> 5;
    const int mh = w >> 3;           // 32-row half
    const int ws = w & 7;            // 16-col strip
    const int lane = tid & 31;
    const int g_id = lane >> 2;
    const int t2 = (lane & 3) << 1;

    // ldmatrix lane role: matrix = lane>>3 -> logical row rl, k-half cl
    const int rl  = ((lane >> 3) & 1) * 8 + (lane & 7);
    const int rlw = rl & 7;
    const uint32_t rbase = (uint32_t)((rl & 8) * 32);
    const int csw = ((lane >> 4) & 1) ^ ((rl >> 2) & 1);

    // staging role: logical row = tid>>3 (0..63; half-private), kt = tid&7.
    const int prow = tid >> 3;
    const int pkt = tid & 7;
    const int plr = prow & 15;
    const int ps  = ((plr >> 2) & 1) ^ ((pkt >> 2) & 1);
    const uint32_t pbo = ablk(prow >> 4, pkt)
                       + (uint32_t)(((plr & 8) | ((plr & 7) ^ pkt)) * 32);
    const uint32_t psts0 = pbo + (uint32_t)(ps * 16);
    const uint32_t psts1 = pbo + (uint32_t)((ps ^ 1) * 16);

    // ---- one-time: combined biases + fp16 weights ----
    {
        float* sb = reinterpret_cast<float*>(smem + OFF_BIAS);
        if (tid < 128) {
            sb[tid]       = bx[tid] + bh[tid];               // u
            sb[128 + tid] = bx[128 + tid] + bh[128 + tid];   // r
            sb[256 + tid] = bx[256 + tid];                   // x_h
            sb[384 + tid] = bh[256 + tid];                   // h_h
        }
    }
    conv_weight(smem, OFF_WX, Wx);
    conv_weight(smem, OFF_WH, Wh);

    const float* sb = reinterpret_cast<const float*>(smem + OFF_BIAS);
    const int stride = gridDim.x;

    // ---- prologue: stage first tile ----
    int tile = blockIdx.x;
    {
        const float* sx = x + ((size_t)tile * 64 + prow) * 128 + pkt * 16;
        const float* sh = h_prev + ((size_t)tile * 64 + prow) * 128 + pkt * 16;
        float4 a0 = __ldcs((const float4*)(sx));
        float4 a1 = __ldcs((const float4*)(sx + 4));
        float4 a2 = __ldcs((const float4*)(sx + 8));
        float4 a3 = __ldcs((const float4*)(sx + 12));
        float4 b0 = __ldcs((const float4*)(sh));
        float4 b1 = __ldcs((const float4*)(sh + 4));
        float4 b2 = __ldcs((const float4*)(sh + 8));
        float4 b3 = __ldcs((const float4*)(sh + 12));
        *reinterpret_cast<uint4*>(smem + OFF_X + psts0) =
            make_uint4(h2u(__floats2half2_rn(a0.x, a0.y)), h2u(__floats2half2_rn(a0.z, a0.w)),
                       h2u(__floats2half2_rn(a1.x, a1.y)), h2u(__floats2half2_rn(a1.z, a1.w)));
        *reinterpret_cast<uint4*>(smem + OFF_X + psts1) =
            make_uint4(h2u(__floats2half2_rn(a2.x, a2.y)), h2u(__floats2half2_rn(a2.z, a2.w)),
                       h2u(__floats2half2_rn(a3.x, a3.y)), h2u(__floats2half2_rn(a3.z, a3.w)));
        *reinterpret_cast<uint4*>(smem + OFF_H + psts0) =
            make_uint4(h2u(__floats2half2_rn(b0.x, b0.y)), h2u(__floats2half2_rn(b0.z, b0.w)),
                       h2u(__floats2half2_rn(b1.x, b1.y)), h2u(__floats2half2_rn(b1.z, b1.w)));
        *reinterpret_cast<uint4*>(smem + OFF_H + psts1) =
            make_uint4(h2u(__floats2half2_rn(b2.x, b2.y)), h2u(__floats2half2_rn(b2.z, b2.w)),
                       h2u(__floats2half2_rn(b3.x, b3.y)), h2u(__floats2half2_rn(b3.z, b3.w)));
    }
    __syncthreads();   // weights + first tiles visible to all

    for (; tile < ntiles; tile += stride) {
        const size_t row0 = (size_t)tile * 64;
        const int nxt = tile + stride;
        const bool hasnext = nxt < ntiles;

        // ---- 1. init accum with bias (broadcast LDS) ----
        float acc[4][2][2][4];
        #pragma unroll
        for (int g = 0; g < 4; g++)
            #pragma unroll
            for (int j = 0; j < 2; j++) {
                float2 bb = *reinterpret_cast<const float2*>(
                    sb + g * 128 + ws * 16 + j * 8 + t2);
                #pragma unroll
                for (int mt = 0; mt < 2; mt++) {
                    acc[g][mt][j][0] = bb.x; acc[g][mt][j][1] = bb.y;
                    acc[g][mt][j][2] = bb.x; acc[g][mt][j][3] = bb.y;
                }
            }
        uint32_t hs[2][4];   // h fragment for epilogue (i==0 -> kt==ws)

        // ---- 2. MMA, per-warp kt rotation; A via ldmatrix ----
        #pragma unroll 1
        for (int i = 0; i < 8; i++) {
            const int kt = (i + ws) & 7;
            const uint32_t aoff = rbase
                + (uint32_t)(((rlw ^ kt) << 5) | ((csw ^ ((kt >> 2) & 1)) << 4));
            const uint32_t lob = (uint32_t)((((lane >> 2) ^ kt) << 5) | ((lane & 3) << 3));
            uint32_t ax[2][4], ah[2][4];
            #pragma unroll
            for (int mt = 0; mt < 2; mt++) {
                uint32_t ab = ablk(mh * 2 + mt, kt) + aoff;
                ldmx4(ax[mt], sb32 + OFF_X + ab);
                ldmx4(ah[mt], sb32 + OFF_H + ab);
            }
            if (i == 0) {   // kt == ws: capture h_prev fragment for epilogue
                #pragma unroll
                for (int mt = 0; mt < 2; mt++)
                    #pragma unroll
                    for (int q = 0; q < 4; q++) hs[mt][q] = ah[mt][q];
            }
            #pragma unroll
            for (int j = 0; j < 2; j++)
                #pragma unroll
                for (int g = 0; g < 3; g++) {
                    int nt = g * 16 + ws * 2 + j;
                    uint2 bxp = *reinterpret_cast<const uint2*>(
                        smem + OFF_WX + (nt * 8 + kt) * 256 + lob);
                    uint2 bhp = *reinterpret_cast<const uint2*>(
                        smem + OFF_WH + (nt * 8 + kt) * 256 + lob);
                    int gh = (g == 2) ? 3 : g;
                    #pragma unroll
                    for (int mt = 0; mt < 2; mt++) {
                        mma16816(acc[g][mt][j],  ax[mt], bxp.x, bxp.y);
                        mma16816(acc[gh][mt][j], ah[mt], bhp.x, bhp.y);
                    }
                }
        }

        // ---- 3. act SMEM now dead for this half: WAR barrier fires EARLY,
        //         removing the epilogue + its skew from the staging path ----
        bar_half(mh);

        // ---- 4. prefetch next x (latency hidden by epilogue) ----
        float4 nx0, nx1, nx2, nx3;
        const float* sxn = x + ((size_t)nxt * 64 + prow) * 128 + pkt * 16;
        if (hasnext) {
            nx0 = __ldcs((const float4*)(sxn));
            nx1 = __ldcs((const float4*)(sxn + 4));
            nx2 = __ldcs((const float4*)(sxn + 8));
            nx3 = __ldcs((const float4*)(sxn + 12));
        }

        // ---- 5. epilogue: fully register-local ----
        #pragma unroll
        for (int mt = 0; mt < 2; mt++) {
            int mtg = mh * 2 + mt;
            int r0 = (int)row0 + mtg * 16 + g_id;
            int r1 = r0 + 8;
            float att0 = __ldg(att + r0);
            float att1 = __ldg(att + r1);
            #pragma unroll
            for (int j = 0; j < 2; j++) {
                int c = ws * 16 + j * 8 + t2;
                float2 hp0 = __half22float2(u2h(hs[mt][2 * j]));
                float2 hp1 = __half22float2(u2h(hs[mt][2 * j + 1]));

                float* uu = acc[0][mt][j];
                float* rr = acc[1][mt][j];
                float* xh = acc[2][mt][j];
                float* hh = acc[3][mt][j];

                float u0 = sigmoid_fast(uu[0]), u1 = sigmoid_fast(uu[1]);
                float u2 = sigmoid_fast(uu[2]), u3 = sigmoid_fast(uu[3]);
                float rg0 = sigmoid_fast(rr[0]), rg1 = sigmoid_fast(rr[1]);
                float rg2 = sigmoid_fast(rr[2]), rg3 = sigmoid_fast(rr[3]);
                float ht0 = tanh_fast(fmaf(rg0, hh[0], xh[0]));
                float ht1 = tanh_fast(fmaf(rg1, hh[1], xh[1]));
                float ht2 = tanh_fast(fmaf(rg2, hh[2], xh[2]));
                float ht3 = tanh_fast(fmaf(rg3, hh[3], xh[3]));

                float2 o0, o1;
                o0.x = fmaf(att0 * u0, ht0 - hp0.x, hp0.x);
                o0.y = fmaf(att0 * u1, ht1 - hp0.y, hp0.y);
                o1.x = fmaf(att1 * u2, ht2 - hp1.x, hp1.x);
                o1.y = fmaf(att1 * u3, ht3 - hp1.y, hp1.y);
                __stcs(reinterpret_cast<float2*>(out + (size_t)r0 * 128 + c), o0);
                __stcs(reinterpret_cast<float2*>(out + (size_t)r1 * 128 + c), o1);
            }
        }

        // ---- 6. prefetch next h; STS both; barrier ----
        float4 nh0, nh1, nh2, nh3;
        const float* shn = h_prev + ((size_t)nxt * 64 + prow) * 128 + pkt * 16;
        if (hasnext) {
            nh0 = __ldcs((const float4*)(shn));
            nh1 = __ldcs((const float4*)(shn + 4));
            nh2 = __ldcs((const float4*)(shn + 8));
            nh3 = __ldcs((const float4*)(shn + 12));
        }
        if (hasnext) {
            *reinterpret_cast<uint4*>(smem + OFF_X + psts0) =
                make_uint4(h2u(__floats2half2_rn(nx0.x, nx0.y)), h2u(__floats2half2_rn(nx0.z, nx0.w)),
                           h2u(__floats2half2_rn(nx1.x, nx1.y)), h2u(__floats2half2_rn(nx1.z, nx1.w)));
            *reinterpret_cast<uint4*>(smem + OFF_X + psts1) =
                make_uint4(h2u(__floats2half2_rn(nx2.x, nx2.y)), h2u(__floats2half2_rn(nx2.z, nx2.w)),
                           h2u(__floats2half2_rn(nx3.x, nx3.y)), h2u(__floats2half2_rn(nx3.z, nx3.w)));
            *reinterpret_cast<uint4*>(smem + OFF_H + psts0) =
                make_uint4(h2u(__floats2half2_rn(nh0.x, nh0.y)), h2u(__floats2half2_rn(nh0.z, nh0.w)),
                           h2u(__floats2half2_rn(nh1.x, nh1.y)), h2u(__floats2half2_rn(nh1.z, nh1.w)));
            *reinterpret_cast<uint4*>(smem + OFF_H + psts1) =
                make_uint4(h2u(__floats2half2_rn(nh2.x, nh2.y)), h2u(__floats2half2_rn(nh2.z, nh2.w)),
                           h2u(__floats2half2_rn(nh3.x, nh3.y)), h2u(__floats2half2_rn(nh3.z, nh3.w)));
        }
        bar_half(mh);          // this half's act blocks staged for next tile
    }
}

extern "C" void kernel_launch(void* const* d_in, const int* in_sizes, int n_in,
                              void* d_out, int out_size) {
    const float* x   = (const float*)d_in[0];
    const float* h   = (const float*)d_in[1];
    const float* att = (const float*)d_in[2];
    const float* Wx  = (const float*)d_in[3];
    const float* bx  = (const float*)d_in[4];
    const float* Wh  = (const float*)d_in[5];
    const float* bh  = (const float*)d_in[6];
    float* out = (float*)d_out;

    int B = in_sizes[2];
    int ntiles = B / 64;

    cudaFuncSetAttribute(augru_kernel, cudaFuncAttributeMaxDynamicSharedMemorySize,
                         SMEM_TOTAL);

    int grid = 148;
    if (grid > ntiles) grid = ntiles;
    augru_kernel<<<grid, 512, SMEM_TOTAL>>>(x, h, att, Wx, bx, Wh, bh, out, ntiles);
}

// round 17
// speedup vs baseline: 1.6278x; 1.6278x over previous
#include <cuda_runtime.h>
#include <cuda_fp16.h>
#include <cstdint>

// ---------------------------------------------------------------------------
// AUGRU cell, sm_103 base-PTX path (no tcgen05 via compute_103).
// mma.sync.m16n8k16 fp16->fp32, persistent CTAs, fp16 weights resident in
// SMEM (paired granule-XOR layout), activations staged per 64-row tile.
//
// R17 vs R14 (best: 57.86us). R16 proved the barrier MUST stay after the
// epilogue (early barrier serializes MMA-skew with the epilogue: 87us).
// R17 keeps R14's structure exactly and fixes the one remaining exposed
// latency: R14 issued the h-prefetch LDG after the epilogue, right before
// bar1, so the post-bar1 STS waited ~600cyc on it. Now BOTH x and h
// prefetch LDGs issue before the epilogue, converted fp32->fp16 at load
// (pxr/phr, 16 regs -- R7-validated pattern); the epilogue (~1.5K cyc)
// hides both, and the bar1->bar2 window is pure STS. This is R15 minus the
// two spill-makers (A double-buffer, hs reload): live set ~110 < 128 regs.
//
// Warp map: w = mh*8+ws; mh = 32-row half, ws = 16-col strip.
// acc[gate 0..3][mt 0..1][j 0..1][4]; gates: 0=u, 1=r, 2=x_h, 3=h_h.
// ---------------------------------------------------------------------------

#define HID 128

// SMEM layout (bytes)
#define OFF_WX   0                    // 48 nt * 8 kt * 256 = 98304 (paired)
#define OFF_WH   98304
#define OFF_BIAS 196608               // 512 floats = 2048
#define OFF_X    198656               // act blocks: (mt*8+kt)*512, 16384 B
#define OFF_H    215040
#define SMEM_TOTAL 231424

static __device__ __forceinline__ uint32_t h2u(__half2 h) {
    return *reinterpret_cast<uint32_t*>(&h);
}
static __device__ __forceinline__ __half2 u2h(uint32_t u) {
    return *reinterpret_cast<__half2*>(&u);
}

static __device__ __forceinline__ uint32_t smem_u32(const void* p) {
    uint32_t a;
    asm("{ .reg .u64 t; cvta.to.shared.u64 t, %1; cvt.u32.u64 %0, t; }"
        : "=r"(a) : "l"(p));
    return a;
}

static __device__ __forceinline__ float tanh_fast(float z) {
    float y;
    asm("tanh.approx.f32 %0, %1;" : "=f"(y) : "f"(z));
    return y;
}
static __device__ __forceinline__ float sigmoid_fast(float z) {
    return fmaf(tanh_fast(0.5f * z), 0.5f, 0.5f);
}

static __device__ __forceinline__ void mma16816(float* c, const uint32_t* a,
                                                uint32_t b0, uint32_t b1) {
    asm volatile(
        "mma.sync.aligned.m16n8k16.row.col.f32.f16.f16.f32 "
        "{%0,%1,%2,%3}, {%4,%5,%6,%7}, {%8,%9}, {%0,%1,%2,%3};"
        : "+f"(c[0]), "+f"(c[1]), "+f"(c[2]), "+f"(c[3])
        : "r"(a[0]), "r"(a[1]), "r"(a[2]), "r"(a[3]), "r"(b0), "r"(b1));
}

static __device__ __forceinline__ void ldmx4(uint32_t* f, uint32_t addr) {
    asm volatile(
        "ldmatrix.sync.aligned.m8n8.x4.shared.b16 {%0,%1,%2,%3}, [%4];"
        : "=r"(f[0]), "=r"(f[1]), "=r"(f[2]), "=r"(f[3]) : "r"(addr));
}

static __device__ __forceinline__ void bar_half(int mh) {
    asm volatile("bar.sync %0, %1;" :: "r"(1 + mh), "r"(256) : "memory");
}

// act fragment block base (512B blocks, disjoint)
static __device__ __forceinline__ uint32_t ablk(int mt, int kt) {
    return (uint32_t)((mt * 8 + kt) * 512);
}

// W fp32 [384,128] row-major -> fp16 B-fragment PAIRED block layout (R11).
// Block (kt, nt) = 256 B at (nt*8 + kt)*256. Lane slot (col g, pair t):
//   offset ((g^kt)&7)*32 + t*8 ; [0:4)=b0 pair (k=2t,2t+1), [4:8)=b1 pair.
static __device__ __forceinline__ void conv_weight(char* smem, uint32_t off,
                                                   const float* __restrict__ W) {
    for (int it = threadIdx.x; it < 384 * 32; it += 512) {
        int n = it >> 5;
        int k4 = (it & 31) << 2;
        int kt = k4 >> 4;
        float4 v = *reinterpret_cast<const float4*>(W + (size_t)n * 128 + k4);
        uint32_t p0 = h2u(__floats2half2_rn(v.x, v.y));
        uint32_t p1 = h2u(__floats2half2_rn(v.z, v.w));
        int t0 = (k4 & 7) >> 1;                           // 0 or 2
        uint32_t hi = (k4 & 8) ? 4u : 0u;                 // b0 vs b1
        uint32_t base = off + (uint32_t)(((n >> 3) * 8 + kt) * 256)
                      + ((uint32_t)((n ^ kt) & 7) << 5) + hi;
        *reinterpret_cast<uint32_t*>(smem + base + (uint32_t)t0 * 8)       = p0;
        *reinterpret_cast<uint32_t*>(smem + base + (uint32_t)(t0 + 1) * 8) = p1;
    }
}

__global__ void __launch_bounds__(512, 1) augru_kernel(
    const float* __restrict__ x, const float* __restrict__ h_prev,
    const float* __restrict__ att, const float* __restrict__ Wx,
    const float* __restrict__ bx, const float* __restrict__ Wh,
    const float* __restrict__ bh, float* __restrict__ out, int ntiles)
{
    extern __shared__ char smem[];
    const uint32_t sb32 = smem_u32(smem);
    const int tid = threadIdx.x;
    const int w = tid >> 5;
    const int mh = w >> 3;           // 32-row half
    const int ws = w & 7;            // 16-col strip
    const int lane = tid & 31;
    const int g_id = lane >> 2;
    const int t2 = (lane & 3) << 1;

    // ldmatrix lane role: matrix = lane>>3 -> logical row rl, k-half cl
    const int rl  = ((lane >> 3) & 1) * 8 + (lane & 7);
    const int rlw = rl & 7;
    const uint32_t rbase = (uint32_t)((rl & 8) * 32);
    const int csw = ((lane >> 4) & 1) ^ ((rl >> 2) & 1);

    // staging role: logical row = tid>>3 (0..63; half-private), kt = tid&7.
    const int prow = tid >> 3;
    const int pkt = tid & 7;
    const int plr = prow & 15;
    const int ps  = ((plr >> 2) & 1) ^ ((pkt >> 2) & 1);
    const uint32_t pbo = ablk(prow >> 4, pkt)
                       + (uint32_t)(((plr & 8) | ((plr & 7) ^ pkt)) * 32);
    const uint32_t psts0 = pbo + (uint32_t)(ps * 16);
    const uint32_t psts1 = pbo + (uint32_t)((ps ^ 1) * 16);

    // ---- one-time: combined biases + fp16 weights ----
    {
        float* sb = reinterpret_cast<float*>(smem + OFF_BIAS);
        if (tid < 128) {
            sb[tid]       = bx[tid] + bh[tid];               // u
            sb[128 + tid] = bx[128 + tid] + bh[128 + tid];   // r
            sb[256 + tid] = bx[256 + tid];                   // x_h
            sb[384 + tid] = bh[256 + tid];                   // h_h
        }
    }
    conv_weight(smem, OFF_WX, Wx);
    conv_weight(smem, OFF_WH, Wh);

    const float* sb = reinterpret_cast<const float*>(smem + OFF_BIAS);
    const int stride = gridDim.x;

    // ---- prologue: stage first tile ----
    int tile = blockIdx.x;
    {
        const float* sx = x + ((size_t)tile * 64 + prow) * 128 + pkt * 16;
        const float* sh = h_prev + ((size_t)tile * 64 + prow) * 128 + pkt * 16;
        float4 a0 = __ldcs((const float4*)(sx));
        float4 a1 = __ldcs((const float4*)(sx + 4));
        float4 a2 = __ldcs((const float4*)(sx + 8));
        float4 a3 = __ldcs((const float4*)(sx + 12));
        float4 b0 = __ldcs((const float4*)(sh));
        float4 b1 = __ldcs((const float4*)(sh + 4));
        float4 b2 = __ldcs((const float4*)(sh + 8));
        float4 b3 = __ldcs((const float4*)(sh + 12));
        *reinterpret_cast<uint4*>(smem + OFF_X + psts0) =
            make_uint4(h2u(__floats2half2_rn(a0.x, a0.y)), h2u(__floats2half2_rn(a0.z, a0.w)),
                       h2u(__floats2half2_rn(a1.x, a1.y)), h2u(__floats2half2_rn(a1.z, a1.w)));
        *reinterpret_cast<uint4*>(smem + OFF_X + psts1) =
            make_uint4(h2u(__floats2half2_rn(a2.x, a2.y)), h2u(__floats2half2_rn(a2.z, a2.w)),
                       h2u(__floats2half2_rn(a3.x, a3.y)), h2u(__floats2half2_rn(a3.z, a3.w)));
        *reinterpret_cast<uint4*>(smem + OFF_H + psts0) =
            make_uint4(h2u(__floats2half2_rn(b0.x, b0.y)), h2u(__floats2half2_rn(b0.z, b0.w)),
                       h2u(__floats2half2_rn(b1.x, b1.y)), h2u(__floats2half2_rn(b1.z, b1.w)));
        *reinterpret_cast<uint4*>(smem + OFF_H + psts1) =
            make_uint4(h2u(__floats2half2_rn(b2.x, b2.y)), h2u(__floats2half2_rn(b2.z, b2.w)),
                       h2u(__floats2half2_rn(b3.x, b3.y)), h2u(__floats2half2_rn(b3.z, b3.w)));
    }
    __syncthreads();   // weights + first tiles visible to all

    for (; tile < ntiles; tile += stride) {
        const size_t row0 = (size_t)tile * 64;
        const int nxt = tile + stride;
        const bool hasnext = nxt < ntiles;

        // ---- 1. init accum with bias (broadcast LDS) ----
        float acc[4][2][2][4];
        #pragma unroll
        for (int g = 0; g < 4; g++)
            #pragma unroll
            for (int j = 0; j < 2; j++) {
                float2 bb = *reinterpret_cast<const float2*>(
                    sb + g * 128 + ws * 16 + j * 8 + t2);
                #pragma unroll
                for (int mt = 0; mt < 2; mt++) {
                    acc[g][mt][j][0] = bb.x; acc[g][mt][j][1] = bb.y;
                    acc[g][mt][j][2] = bb.x; acc[g][mt][j][3] = bb.y;
                }
            }
        uint32_t hs[2][4];   // h fragment for epilogue (i==0 -> kt==ws)

        // ---- 2. MMA, per-warp kt rotation; A via ldmatrix ----
        #pragma unroll 1
        for (int i = 0; i < 8; i++) {
            const int kt = (i + ws) & 7;
            const uint32_t aoff = rbase
                + (uint32_t)(((rlw ^ kt) << 5) | ((csw ^ ((kt >> 2) & 1)) << 4));
            const uint32_t lob = (uint32_t)((((lane >> 2) ^ kt) << 5) | ((lane & 3) << 3));
            uint32_t ax[2][4], ah[2][4];
            #pragma unroll
            for (int mt = 0; mt < 2; mt++) {
                uint32_t ab = ablk(mh * 2 + mt, kt) + aoff;
                ldmx4(ax[mt], sb32 + OFF_X + ab);
                ldmx4(ah[mt], sb32 + OFF_H + ab);
            }
            if (i == 0) {   // kt == ws: capture h_prev fragment for epilogue
                #pragma unroll
                for (int mt = 0; mt < 2; mt++)
                    #pragma unroll
                    for (int q = 0; q < 4; q++) hs[mt][q] = ah[mt][q];
            }
            #pragma unroll
            for (int j = 0; j < 2; j++)
                #pragma unroll
                for (int g = 0; g < 3; g++) {
                    int nt = g * 16 + ws * 2 + j;
                    uint2 bxp = *reinterpret_cast<const uint2*>(
                        smem + OFF_WX + (nt * 8 + kt) * 256 + lob);
                    uint2 bhp = *reinterpret_cast<const uint2*>(
                        smem + OFF_WH + (nt * 8 + kt) * 256 + lob);
                    int gh = (g == 2) ? 3 : g;
                    #pragma unroll
                    for (int mt = 0; mt < 2; mt++) {
                        mma16816(acc[g][mt][j],  ax[mt], bxp.x, bxp.y);
                        mma16816(acc[gh][mt][j], ah[mt], bhp.x, bhp.y);
                    }
                }
        }

        // ---- 3. prefetch next x AND h -> fp16 regs (hidden by epilogue) ----
        uint32_t pxr[8], phr[8];
        if (hasnext) {
            const float* sxn = x + ((size_t)nxt * 64 + prow) * 128 + pkt * 16;
            const float* shn = h_prev + ((size_t)nxt * 64 + prow) * 128 + pkt * 16;
            float4 a0 = __ldcs((const float4*)(sxn));
            float4 a1 = __ldcs((const float4*)(sxn + 4));
            float4 a2 = __ldcs((const float4*)(sxn + 8));
            float4 a3 = __ldcs((const float4*)(sxn + 12));
            float4 b0 = __ldcs((const float4*)(shn));
            float4 b1 = __ldcs((const float4*)(shn + 4));
            float4 b2 = __ldcs((const float4*)(shn + 8));
            float4 b3 = __ldcs((const float4*)(shn + 12));
            pxr[0] = h2u(__floats2half2_rn(a0.x, a0.y)); pxr[1] = h2u(__floats2half2_rn(a0.z, a0.w));
            pxr[2] = h2u(__floats2half2_rn(a1.x, a1.y)); pxr[3] = h2u(__floats2half2_rn(a1.z, a1.w));
            pxr[4] = h2u(__floats2half2_rn(a2.x, a2.y)); pxr[5] = h2u(__floats2half2_rn(a2.z, a2.w));
            pxr[6] = h2u(__floats2half2_rn(a3.x, a3.y)); pxr[7] = h2u(__floats2half2_rn(a3.z, a3.w));
            phr[0] = h2u(__floats2half2_rn(b0.x, b0.y)); phr[1] = h2u(__floats2half2_rn(b0.z, b0.w));
            phr[2] = h2u(__floats2half2_rn(b1.x, b1.y)); phr[3] = h2u(__floats2half2_rn(b1.z, b1.w));
            phr[4] = h2u(__floats2half2_rn(b2.x, b2.y)); phr[5] = h2u(__floats2half2_rn(b2.z, b2.w));
            phr[6] = h2u(__floats2half2_rn(b3.x, b3.y)); phr[7] = h2u(__floats2half2_rn(b3.z, b3.w));
        }

        // ---- 4. epilogue: fully register-local (hides prefetch latency) ----
        #pragma unroll
        for (int mt = 0; mt < 2; mt++) {
            int mtg = mh * 2 + mt;
            int r0 = (int)row0 + mtg * 16 + g_id;
            int r1 = r0 + 8;
            float att0 = __ldg(att + r0);
            float att1 = __ldg(att + r1);
            #pragma unroll
            for (int j = 0; j < 2; j++) {
                int c = ws * 16 + j * 8 + t2;
                float2 hp0 = __half22float2(u2h(hs[mt][2 * j]));
                float2 hp1 = __half22float2(u2h(hs[mt][2 * j + 1]));

                float* uu = acc[0][mt][j];
                float* rr = acc[1][mt][j];
                float* xh = acc[2][mt][j];
                float* hh = acc[3][mt][j];

                float u0 = sigmoid_fast(uu[0]), u1 = sigmoid_fast(uu[1]);
                float u2 = sigmoid_fast(uu[2]), u3 = sigmoid_fast(uu[3]);
                float rg0 = sigmoid_fast(rr[0]), rg1 = sigmoid_fast(rr[1]);
                float rg2 = sigmoid_fast(rr[2]), rg3 = sigmoid_fast(rr[3]);
                float ht0 = tanh_fast(fmaf(rg0, hh[0], xh[0]));
                float ht1 = tanh_fast(fmaf(rg1, hh[1], xh[1]));
                float ht2 = tanh_fast(fmaf(rg2, hh[2], xh[2]));
                float ht3 = tanh_fast(fmaf(rg3, hh[3], xh[3]));

                float2 o0, o1;
                o0.x = fmaf(att0 * u0, ht0 - hp0.x, hp0.x);
                o0.y = fmaf(att0 * u1, ht1 - hp0.y, hp0.y);
                o1.x = fmaf(att1 * u2, ht2 - hp1.x, hp1.x);
                o1.y = fmaf(att1 * u3, ht3 - hp1.y, hp1.y);
                __stcs(reinterpret_cast<float2*>(out + (size_t)r0 * 128 + c), o0);
                __stcs(reinterpret_cast<float2*>(out + (size_t)r1 * 128 + c), o1);
            }
        }

        // ---- 5. per-half barrier; pure-STS window; barrier ----
        bar_half(mh);          // this half's warps done reading act blocks
        if (hasnext) {
            *reinterpret_cast<uint4*>(smem + OFF_X + psts0) =
                make_uint4(pxr[0], pxr[1], pxr[2], pxr[3]);
            *reinterpret_cast<uint4*>(smem + OFF_X + psts1) =
                make_uint4(pxr[4], pxr[5], pxr[6], pxr[7]);
            *reinterpret_cast<uint4*>(smem + OFF_H + psts0) =
                make_uint4(phr[0], phr[1], phr[2], phr[3]);
            *reinterpret_cast<uint4*>(smem + OFF_H + psts1) =
                make_uint4(phr[4], phr[5], phr[6], phr[7]);
        }
        bar_half(mh);          // this half's act blocks staged for next tile
    }
}

extern "C" void kernel_launch(void* const* d_in, const int* in_sizes, int n_in,
                              void* d_out, int out_size) {
    const float* x   = (const float*)d_in[0];
    const float* h   = (const float*)d_in[1];
    const float* att = (const float*)d_in[2];
    const float* Wx  = (const float*)d_in[3];
    const float* bx  = (const float*)d_in[4];
    const float* Wh  = (const float*)d_in[5];
    const float* bh  = (const float*)d_in[6];
    float* out = (float*)d_out;

    int B = in_sizes[2];
    int ntiles = B / 64;

    cudaFuncSetAttribute(augru_kernel, cudaFuncAttributeMaxDynamicSharedMemorySize,
                         SMEM_TOTAL);

    int grid = 148;
    if (grid > ntiles) grid = ntiles;
    augru_kernel<<<grid, 512, SMEM_TOTAL>>>(x, h, att, Wx, bx, Wh, bh, out, ntiles);
}